// round 1
// baseline (speedup 1.0000x reference)
#include <cuda_runtime.h>
#include <cstdint>

#define NB   64
#define TSEQ 1024
#define HID  512      // 2H
#define KC   48
#define TJ   128

// ---------------- device scratch (static, allocation-free) ----------------
__device__ float g_t1[NB * 512];
__device__ float g_pre[NB * 256];
__device__ float g_out_att[NB * 512];
__device__ float g_attW[NB * 512];
__device__ float g_wexp[NB * TSEQ];
__device__ float g_winv[NB];
__device__ float g_attn_part[NB * 8 * 512];
__device__ float g_attn[NB * 512];
__device__ float g_outdec[NB * 1152];
__device__ float g_res1[NB * 512];
__device__ float g_res2[NB * 512];
__device__ float g_P[24 * NB * 2048];   // GEMM k-split partials (max 24 splits x 64 x 2048)

__device__ __forceinline__ float tanh_fast(float x) {
    float y; asm("tanh.approx.f32 %0, %1;" : "=f"(y) : "f"(x)); return y;
}
__device__ __forceinline__ float sigmoid_f(float x) { return 1.f / (1.f + __expf(-x)); }

// ---------------- generic k-split partial GEMM:  P[s][n][jofs+j] = X[n][k0:k0+kn] . W[j][k0:k0+kn]
// X: [64][ldx] row-major, W: [M][ldw] row-major. 128 threads, block tile 128j x 64n, thread tile 8j x 8n.
__global__ void gemm_part(const float* __restrict__ X, int ldx,
                          const float* __restrict__ W, int ldw,
                          float* __restrict__ P, int ldp,
                          int jofs, int sofs, int M, int K)
{
    __shared__ float xs[KC][68];
    __shared__ float ws[TJ][KC + 1];
    const int tid = threadIdx.x;
    const int jt0 = blockIdx.x * TJ;
    const int k0  = blockIdx.y * KC;
    const int kn  = min(KC, K - k0);
    const int nv  = kn >> 2;   // float4 per row (all K values are multiples of 4)

    for (int idx = tid; idx < 64 * nv; idx += 128) {
        int n = idx / nv, kk = (idx - n * nv) * 4;
        float4 v = *reinterpret_cast<const float4*>(X + (size_t)n * ldx + k0 + kk);
        xs[kk + 0][n] = v.x; xs[kk + 1][n] = v.y; xs[kk + 2][n] = v.z; xs[kk + 3][n] = v.w;
    }
    for (int idx = tid; idx < TJ * nv; idx += 128) {
        int j = idx / nv, kk = (idx - j * nv) * 4;
        int jr = jt0 + j; if (jr >= M) jr = M - 1;   // clamp (writes guarded later)
        float4 v = *reinterpret_cast<const float4*>(W + (size_t)jr * ldw + k0 + kk);
        ws[j][kk + 0] = v.x; ws[j][kk + 1] = v.y; ws[j][kk + 2] = v.z; ws[j][kk + 3] = v.w;
    }
    __syncthreads();

    const int nt = tid & 7;    // 8 n-groups of 8
    const int jt = tid >> 3;   // 16 j-groups of 8
    float acc[8][8];
#pragma unroll
    for (int a = 0; a < 8; a++)
#pragma unroll
        for (int b = 0; b < 8; b++) acc[a][b] = 0.f;

#pragma unroll 4
    for (int k = 0; k < kn; k++) {
        float4 xa = *reinterpret_cast<const float4*>(&xs[k][nt * 8]);
        float4 xb = *reinterpret_cast<const float4*>(&xs[k][nt * 8 + 4]);
        float xv[8] = {xa.x, xa.y, xa.z, xa.w, xb.x, xb.y, xb.z, xb.w};
#pragma unroll
        for (int jj = 0; jj < 8; jj++) {
            float wv = ws[jt * 8 + jj][k];
#pragma unroll
            for (int i = 0; i < 8; i++) acc[jj][i] += wv * xv[i];
        }
    }

    float* p = P + (size_t)(sofs + blockIdx.y) * 64 * ldp + jofs + jt0;
    int jbase = jt0 + jt * 8;
#pragma unroll
    for (int i = 0; i < 8; i++) {
        int n = nt * 8 + i;
        float* pr = p + (size_t)n * ldp + jt * 8;
        if (jbase < M)
            *reinterpret_cast<float4*>(pr)     = make_float4(acc[0][i], acc[1][i], acc[2][i], acc[3][i]);
        if (jbase + 4 < M)
            *reinterpret_cast<float4*>(pr + 4) = make_float4(acc[4][i], acc[5][i], acc[6][i], acc[7][i]);
    }
}

// ---------------- partial-sum epilogues ----------------
__global__ void k_red_act(const float* __restrict__ P, int ldp, int ns, int M,
                          const float* __restrict__ bias, float* __restrict__ out, int relu)
{
    int idx = blockIdx.x * blockDim.x + threadIdx.x;
    if (idx >= 64 * M) return;
    int n = idx / M, j = idx - n * M;
    float s = bias[j];
    for (int t = 0; t < ns; t++) s += P[(size_t)t * 64 * ldp + (size_t)n * ldp + j];
    out[idx] = relu ? fmaxf(s, 0.f) : s;
}

// GRU epilogue with h=0:  out = (1-z)*tanh(gn + r*bhh_n) [+ resin]
__global__ void k_red_gru(const float* __restrict__ P, int ldp, int ns,
                          const float* __restrict__ bih, const float* __restrict__ bhh,
                          const float* __restrict__ resin, float* __restrict__ out)
{
    int idx = blockIdx.x * blockDim.x + threadIdx.x;
    if (idx >= 64 * 512) return;
    int n = idx >> 9, j = idx & 511;
    float gr = bih[j], gz = bih[512 + j], gn = bih[1024 + j];
    for (int t = 0; t < ns; t++) {
        const float* pp = P + (size_t)t * 64 * ldp + (size_t)n * ldp;
        gr += pp[j]; gz += pp[512 + j]; gn += pp[1024 + j];
    }
    float r  = sigmoid_f(gr + bhh[j]);
    float z  = sigmoid_f(gz + bhh[512 + j]);
    float nn = tanhf(gn + r * bhh[1024 + j]);
    float o  = (1.f - z) * nn;
    if (resin) o += resin[idx];
    out[idx] = o;
}

// residual = (wsc GEMM + bsc) + gru1(out_dec).  P cols: [0:512)=sc, [512:2048)=g1 gates. ldp=2048.
__global__ void k_red_scgru(const float* __restrict__ P, int ns,
                            const float* __restrict__ bsc,
                            const float* __restrict__ bih, const float* __restrict__ bhh,
                            float* __restrict__ out)
{
    int idx = blockIdx.x * blockDim.x + threadIdx.x;
    if (idx >= 64 * 512) return;
    int n = idx >> 9, j = idx & 511;
    float sc = bsc[j], gr = bih[j], gz = bih[512 + j], gn = bih[1024 + j];
    for (int t = 0; t < ns; t++) {
        const float* pp = P + (size_t)t * 64 * 2048 + (size_t)n * 2048;
        sc += pp[j]; gr += pp[512 + j]; gz += pp[1024 + j]; gn += pp[1536 + j];
    }
    float r  = sigmoid_f(gr + bhh[j]);
    float z  = sigmoid_f(gz + bhh[512 + j]);
    float nn = tanhf(gn + r * bhh[1024 + j]);
    out[idx] = sc + (1.f - z) * nn;
}

// ---------------- attention ----------------
// wexp[n][t] = exp(wattn . tanh(encW[n][t] + attW[n]) + battn) * (t < len)
__global__ void k_score(const float* __restrict__ encW, const float* __restrict__ wattn,
                        const float* __restrict__ battn, const int* __restrict__ len)
{
    int n = blockIdx.x, t0 = blockIdx.y * 64;
    __shared__ float a_s[512], w_s[512];
    int tid = threadIdx.x;                       // 256
    a_s[tid] = g_attW[n * 512 + tid];   a_s[tid + 256] = g_attW[n * 512 + tid + 256];
    w_s[tid] = wattn[tid];              w_s[tid + 256] = wattn[tid + 256];
    __syncthreads();
    int L = len[n];
    int warp = tid >> 5, lane = tid & 31;
    float bat = battn[0];
    for (int tt = warp; tt < 64; tt += 8) {
        int t = t0 + tt;
        if (t < L) {
            const float* row = encW + ((size_t)n * TSEQ + t) * 512;
            float s = 0.f;
#pragma unroll
            for (int q = 0; q < 4; q++) {
                int c = (lane + q * 32) * 4;
                float4 v  = *reinterpret_cast<const float4*>(row + c);
                float4 av = *reinterpret_cast<const float4*>(&a_s[c]);
                float4 wv = *reinterpret_cast<const float4*>(&w_s[c]);
                s += tanh_fast(v.x + av.x) * wv.x
                   + tanh_fast(v.y + av.y) * wv.y
                   + tanh_fast(v.z + av.z) * wv.z
                   + tanh_fast(v.w + av.w) * wv.w;
            }
#pragma unroll
            for (int o = 16; o > 0; o >>= 1) s += __shfl_xor_sync(0xffffffffu, s, o);
            if (lane == 0) g_wexp[n * TSEQ + t] = __expf(s + bat);
        } else if (lane == 0) {
            g_wexp[n * TSEQ + t] = 0.f;
        }
    }
}

__global__ void k_wsum()
{
    int n = blockIdx.x, tid = threadIdx.x;       // 256
    float s = 0.f;
    for (int t = tid; t < TSEQ; t += 256) s += g_wexp[n * TSEQ + t];
    __shared__ float sm[256];
    sm[tid] = s; __syncthreads();
    for (int o = 128; o > 0; o >>= 1) { if (tid < o) sm[tid] += sm[tid + o]; __syncthreads(); }
    if (tid == 0) g_winv[n] = 1.f / fmaxf(sm[0], 1e-12f);
}

__global__ void k_attnpart(const float* __restrict__ enc, const int* __restrict__ len)
{
    int n = blockIdx.x, ch = blockIdx.y;
    int t0 = ch * 128, tid = threadIdx.x;        // 512
    int L = len[n];
    float acc = 0.f;
    if (t0 < L) {
        int tc = min(128, L - t0);
        __shared__ float wsm[128];
        if (tid < 128) wsm[tid] = g_wexp[n * TSEQ + t0 + tid];
        __syncthreads();
        const float* base = enc + ((size_t)n * TSEQ + t0) * 512 + tid;
        int i = 0;
        for (; i + 4 <= tc; i += 4) {
            float v0 = base[(i + 0) * 512], v1 = base[(i + 1) * 512];
            float v2 = base[(i + 2) * 512], v3 = base[(i + 3) * 512];
            acc += wsm[i] * v0 + wsm[i + 1] * v1 + wsm[i + 2] * v2 + wsm[i + 3] * v3;
        }
        for (; i < tc; i++) acc += wsm[i] * base[i * 512];
    }
    g_attn_part[((size_t)n * 8 + ch) * 512 + tid] = acc;
}

__global__ void k_attnred(float* __restrict__ dout)
{
    int n = blockIdx.x, tid = threadIdx.x;       // 512
    float s = 0.f;
#pragma unroll
    for (int ch = 0; ch < 8; ch++) s += g_attn_part[((size_t)n * 8 + ch) * 512 + tid];
    float v = s * g_winv[n];
    g_attn[n * 512 + tid] = v;
    dout[64 * 160 + n * 512 + tid] = v;          // attn_applied section of output
}

__global__ void k_concat(const float* __restrict__ sv)
{
    int idx = blockIdx.x * blockDim.x + threadIdx.x;
    if (idx >= 64 * 1152) return;
    int n = idx / 1152, c = idx - n * 1152;
    float v;
    if (c < 512)       v = g_attn[n * 512 + c];
    else if (c < 1024) v = g_out_att[n * 512 + (c - 512)];
    else               v = sv[n * 128 + (c - 1024)];
    g_outdec[idx] = v;
}

// ---------------- host orchestration ----------------
extern "C" void kernel_launch(void* const* d_in, const int* in_sizes, int n_in,
                              void* d_out, int out_size)
{
    (void)n_in; (void)out_size;
    // metadata order dispatch: dict order has lengths_enc (64 ints) at index 4;
    // reference-signature order has pw1 (40960) there and lengths last.
    bool dictord = (in_sizes[4] == 64);
    int b = dictord ? 5 : 4;
    const float* input_enc  = (const float*)d_in[0];
    const float* input_attW = (const float*)d_in[1];
    const float* input_dec  = (const float*)d_in[2];
    const float* style      = (const float*)d_in[3];
    const int*   lengths    = (const int*)(dictord ? d_in[4] : d_in[28]);
    const float* pw1   = (const float*)d_in[b + 0];
    const float* pb1   = (const float*)d_in[b + 1];
    const float* pw2   = (const float*)d_in[b + 2];
    const float* pb2   = (const float*)d_in[b + 3];
    const float* wdec  = (const float*)d_in[b + 4];
    const float* bdec  = (const float*)d_in[b + 5];
    const float* ga_ih = (const float*)d_in[b + 6];
    const float* ga_bih= (const float*)d_in[b + 8];
    const float* ga_bhh= (const float*)d_in[b + 9];
    const float* wattn = (const float*)d_in[b + 10];
    const float* battn = (const float*)d_in[b + 11];
    const float* wsc   = (const float*)d_in[b + 12];
    const float* bsc   = (const float*)d_in[b + 13];
    const float* g1_ih = (const float*)d_in[b + 14];
    const float* g1_bih= (const float*)d_in[b + 16];
    const float* g1_bhh= (const float*)d_in[b + 17];
    const float* g2_ih = (const float*)d_in[b + 18];
    const float* g2_bih= (const float*)d_in[b + 20];
    const float* g2_bhh= (const float*)d_in[b + 21];
    const float* wout  = (const float*)d_in[b + 22];
    const float* bout  = (const float*)d_in[b + 23];

    float *P, *t1, *pre, *oatt, *attW, *odec, *res1, *res2;
    cudaGetSymbolAddress((void**)&P,    g_P);
    cudaGetSymbolAddress((void**)&t1,   g_t1);
    cudaGetSymbolAddress((void**)&pre,  g_pre);
    cudaGetSymbolAddress((void**)&oatt, g_out_att);
    cudaGetSymbolAddress((void**)&attW, g_attW);
    cudaGetSymbolAddress((void**)&odec, g_outdec);
    cudaGetSymbolAddress((void**)&res1, g_res1);
    cudaGetSymbolAddress((void**)&res2, g_res2);
    float* out = (float*)d_out;

    // prenet layer 1: t1 = relu(dec @ pw1.T + pb1)   [64,512], K=80
    gemm_part<<<dim3(4, 2), 128>>>(input_dec, 80, pw1, 80, P, 512, 0, 0, 512, 80);
    k_red_act<<<128, 256>>>(P, 512, 2, 512, pb1, t1, 1);
    // prenet layer 2: pre = relu(t1 @ pw2.T + pb2)   [64,256], K=512
    gemm_part<<<dim3(2, 11), 128>>>(t1, 512, pw2, 512, P, 256, 0, 0, 256, 512);
    k_red_act<<<64, 256>>>(P, 256, 11, 256, pb2, pre, 1);
    // GRU-A input GEMM (ctx0=0 -> only cols 0:256 and 768:896 of ga_ih live)
    gemm_part<<<dim3(12, 6), 128>>>(pre, 256, ga_ih, 896, P, 1536, 0, 0, 1536, 256);
    gemm_part<<<dim3(12, 3), 128>>>(style, 128, ga_ih + 768, 896, P, 1536, 0, 6, 1536, 128);
    k_red_gru<<<128, 256>>>(P, 1536, 9, ga_bih, ga_bhh, nullptr, oatt);
    // attW_dec = out_att @ wdec.T + bdec
    gemm_part<<<dim3(4, 11), 128>>>(oatt, 512, wdec, 512, P, 512, 0, 0, 512, 512);
    k_red_act<<<128, 256>>>(P, 512, 11, 512, bdec, attW, 0);
    // attention
    k_score<<<dim3(64, 16), 256>>>(input_attW, wattn, battn, lengths);
    k_wsum<<<64, 256>>>();
    k_attnpart<<<dim3(64, 8), 512>>>(input_enc, lengths);
    k_attnred<<<64, 512>>>(out);
    // out_dec = [attn | out_att | sv]
    k_concat<<<288, 256>>>(style);
    // residual = out_dec@wsc.T+bsc ; h1 = gru1(out_dec) ; res1 = residual + h1  (fused M=2048 GEMM)
    gemm_part<<<dim3(4, 24), 128>>>(odec, 1152, wsc,   1152, P, 2048, 0,   0, 512,  1152);
    gemm_part<<<dim3(12, 24), 128>>>(odec, 1152, g1_ih, 1152, P, 2048, 512, 0, 1536, 1152);
    k_red_scgru<<<128, 256>>>(P, 24, bsc, g1_bih, g1_bhh, res1);
    // h2 = gru2(res1); res2 = res1 + h2
    gemm_part<<<dim3(12, 11), 128>>>(res1, 512, g2_ih, 512, P, 1536, 0, 0, 1536, 512);
    k_red_gru<<<128, 256>>>(P, 1536, 11, g2_bih, g2_bhh, res1, res2);
    // output = res2 @ wout.T + bout  -> d_out[0:10240)
    gemm_part<<<dim3(2, 11), 128>>>(res2, 512, wout, 512, P, 160, 0, 0, 160, 512);
    k_red_act<<<40, 256>>>(P, 160, 11, 160, bout, out, 0);
}